// round 2
// baseline (speedup 1.0000x reference)
#include <cuda_runtime.h>
#include <math.h>

#define BB   4
#define CC   256
#define CSd  128
#define NN   4096
#define EPSc 1e-5f

// ---------------- scratch (device globals; no allocations) ----------------
__device__ float d_Q[BB*CSd*NN];   // [b][cs][n] dim-major
__device__ float d_K[BB*CSd*NN];   // [b][cs][n] dim-major
__device__ float d_V[BB*NN*CSd];   // [b][n][cs] token-major
__device__ float d_O[BB*NN*CSd];   // [b][n][cs] token-major
__device__ float d_Y[BB*CC*NN];    // [b][c][n]
__device__ float d_scale[CC];
__device__ float d_shift[CC];

// ======================= Kernel A: QKV projections =========================
// grid (N/128, B, 3), block 256. Out tile 128(cs) x 128(n), 8x8 microtile.
__global__ __launch_bounds__(256) void qkv_kernel(
    const float* __restrict__ x,
    const float* __restrict__ Wq, const float* __restrict__ bq,
    const float* __restrict__ Wk, const float* __restrict__ bk,
    const float* __restrict__ Wv, const float* __restrict__ bv)
{
    __shared__ float Ws[128*36];   // Ws[cs][kc]
    __shared__ float Xs[32*132];   // Xs[kc][n]
    const int z  = blockIdx.z;     // 0=Q 1=K 2=V
    const int b  = blockIdx.y;
    const int n0 = blockIdx.x * 128;
    const float* W    = (z==0) ? Wq : (z==1) ? Wk : Wv;
    const float* bias = (z==0) ? bq : (z==1) ? bk : bv;
    const int tid = threadIdx.x;
    const int ty = tid >> 4, tx = tid & 15;

    float acc[8][8];
    #pragma unroll
    for (int i = 0; i < 8; i++)
        #pragma unroll
        for (int j = 0; j < 8; j++) acc[i][j] = 0.f;

    for (int k0 = 0; k0 < CC; k0 += 32) {
        #pragma unroll
        for (int it = 0; it < 16; it++) {
            int f = tid + it*256;
            int kc = f & 31, cs = f >> 5;
            Ws[cs*36 + kc] = W[cs*CC + k0 + kc];
        }
        #pragma unroll
        for (int it = 0; it < 16; it++) {
            int f = tid + it*256;
            int nn2 = f & 127, kc = f >> 7;
            Xs[kc*132 + nn2] = x[(b*CC + k0 + kc)*NN + n0 + nn2];
        }
        __syncthreads();
        #pragma unroll 8
        for (int kc = 0; kc < 32; kc++) {
            float a[8];
            #pragma unroll
            for (int i = 0; i < 8; i++) a[i] = Ws[(ty*8+i)*36 + kc];
            float4 b0 = *(const float4*)&Xs[kc*132 + tx*8];
            float4 b1 = *(const float4*)&Xs[kc*132 + tx*8 + 4];
            float bbv[8] = {b0.x,b0.y,b0.z,b0.w,b1.x,b1.y,b1.z,b1.w};
            #pragma unroll
            for (int i = 0; i < 8; i++)
                #pragma unroll
                for (int j = 0; j < 8; j++)
                    acc[i][j] = fmaf(a[i], bbv[j], acc[i][j]);
        }
        __syncthreads();
    }

    float bl[8];
    #pragma unroll
    for (int i = 0; i < 8; i++) bl[i] = bias[ty*8 + i];

    if (z < 2) {
        float* out = (z==0) ? d_Q : d_K;
        #pragma unroll
        for (int i = 0; i < 8; i++) {
            int cs = ty*8 + i;
            float* p = &out[(b*CSd + cs)*NN + n0 + tx*8];
            *(float4*)p       = make_float4(acc[i][0]+bl[i], acc[i][1]+bl[i], acc[i][2]+bl[i], acc[i][3]+bl[i]);
            *((float4*)p + 1) = make_float4(acc[i][4]+bl[i], acc[i][5]+bl[i], acc[i][6]+bl[i], acc[i][7]+bl[i]);
        }
    } else {
        #pragma unroll
        for (int j = 0; j < 8; j++) {
            int n = n0 + tx*8 + j;
            float* p = &d_V[(b*NN + n)*CSd + ty*8];
            *(float4*)p       = make_float4(acc[0][j]+bl[0], acc[1][j]+bl[1], acc[2][j]+bl[2], acc[3][j]+bl[3]);
            *((float4*)p + 1) = make_float4(acc[4][j]+bl[4], acc[5][j]+bl[5], acc[6][j]+bl[6], acc[7][j]+bl[7]);
        }
    }
}

// ======================= Kernel B: flash attention (fp32) ==================
// grid (N/64, B), block 256. BM=64 queries, BN=64 keys, d=128.
// Microtiles: S 4x4 (64x64 = 256*16 exact), PV 4x8 (64x128 = 256*32 exact).
#define QT_STRIDE 64
#define KT_STRIDE 64
#define VS_STRIDE 128
#define ST_STRIDE 68
// floats: Qt 128*64 + Kt 128*64 + Vs 64*128 + St 64*68 + 3*64
#define ATTN_SMEM_FLOATS (128*QT_STRIDE + 128*KT_STRIDE + 64*VS_STRIDE + 64*ST_STRIDE + 192)
#define ATTN_SMEM_BYTES  (ATTN_SMEM_FLOATS*4)

__global__ __launch_bounds__(256) void attn_kernel()
{
    extern __shared__ float sm[];
    float* Qt    = sm;                      // [128][64]  Qt[dim][qrow]
    float* Kt    = Qt + 128*QT_STRIDE;      // [128][64]  Kt[dim][key]
    float* Vs    = Kt + 128*KT_STRIDE;      // [64][128]  Vs[key][dim]
    float* St    = Vs + 64*VS_STRIDE;       // [64][68]   St[qrow][key]
    float* mrow  = St + 64*ST_STRIDE;       // [64]
    float* lrow  = mrow + 64;               // [64]
    float* rsrow = lrow + 64;               // [64]

    const int b  = blockIdx.y;
    const int q0 = blockIdx.x * 64;
    const int tid = threadIdx.x;
    const int ty = tid >> 4, tx = tid & 15;   // ty: 16 q-groups of 4, tx: 16 key/dim groups

    // load Q tile, dim-major (coalesced: consecutive tid -> consecutive token)
    #pragma unroll
    for (int it = 0; it < 32; it++) {
        int f = tid + it*256;                 // 0..8191
        int q = f & 63, cs = f >> 6;
        Qt[cs*QT_STRIDE + q] = d_Q[(b*CSd + cs)*NN + q0 + q];
    }
    if (tid < 64) { mrow[tid] = -1e30f; lrow[tid] = 0.f; }

    float o[4][8];
    #pragma unroll
    for (int i = 0; i < 4; i++)
        #pragma unroll
        for (int j = 0; j < 8; j++) o[i][j] = 0.f;

    for (int kt = 0; kt < NN/64; kt++) {
        const int kb = kt * 64;
        __syncthreads();   // prev PV done (Vs/St free); Qt ready on iter 0
        #pragma unroll
        for (int it = 0; it < 32; it++) {
            int f = tid + it*256;
            int kk = f & 63, cs = f >> 6;
            Kt[cs*KT_STRIDE + kk] = d_K[(b*CSd + cs)*NN + kb + kk];
        }
        #pragma unroll
        for (int it = 0; it < 32; it++) {
            int f = tid + it*256;
            int cs = f & 127, kk = f >> 7;
            Vs[kk*VS_STRIDE + cs] = d_V[(b*NN + kb + kk)*CSd + cs];
        }
        __syncthreads();

        // ---- S = Q (64x128)^T-free . K (128x64): 4x4 microtile ----
        float s[4][4];
        #pragma unroll
        for (int i = 0; i < 4; i++)
            #pragma unroll
            for (int j = 0; j < 4; j++) s[i][j] = 0.f;
        #pragma unroll 4
        for (int k = 0; k < 128; k++) {
            float4 a  = *(const float4*)&Qt[k*QT_STRIDE + ty*4];
            float4 kv = *(const float4*)&Kt[k*KT_STRIDE + tx*4];
            float av[4]  = {a.x,a.y,a.z,a.w};
            float bv2[4] = {kv.x,kv.y,kv.z,kv.w};
            #pragma unroll
            for (int i = 0; i < 4; i++)
                #pragma unroll
                for (int j = 0; j < 4; j++)
                    s[i][j] = fmaf(av[i], bv2[j], s[i][j]);
        }
        // store logits row-major: St[q][key]
        #pragma unroll
        for (int i = 0; i < 4; i++)
            *(float4*)&St[(ty*4+i)*ST_STRIDE + tx*4] =
                make_float4(s[i][0], s[i][1], s[i][2], s[i][3]);
        __syncthreads();

        // ---- online softmax: 4 threads per row, 16 keys each ----
        {
            const int r = tid >> 2, sub = tid & 3;
            const int cb = sub * 16;
            float* row = &St[r*ST_STRIDE + cb];
            float tm = -1e30f;
            #pragma unroll
            for (int c2 = 0; c2 < 16; c2++) tm = fmaxf(tm, row[c2]);
            tm = fmaxf(tm, __shfl_xor_sync(0xffffffffu, tm, 1));
            tm = fmaxf(tm, __shfl_xor_sync(0xffffffffu, tm, 2));
            float mo = mrow[r];
            float nm = fmaxf(mo, tm);
            float sum = 0.f;
            #pragma unroll
            for (int c2 = 0; c2 < 16; c2++) {
                float p = __expf(row[c2] - nm);
                row[c2] = p;
                sum += p;
            }
            sum += __shfl_xor_sync(0xffffffffu, sum, 1);
            sum += __shfl_xor_sync(0xffffffffu, sum, 2);
            if (sub == 0) {
                float scv = __expf(mo - nm);
                lrow[r] = lrow[r]*scv + sum;
                mrow[r] = nm;
                rsrow[r] = scv;
            }
        }
        __syncthreads();

        // ---- rescale, then O += P (64x64) . V (64x128): 4x8 microtile ----
        float scl[4];
        #pragma unroll
        for (int i = 0; i < 4; i++) scl[i] = rsrow[ty*4 + i];
        #pragma unroll
        for (int i = 0; i < 4; i++)
            #pragma unroll
            for (int j = 0; j < 8; j++) o[i][j] *= scl[i];

        #pragma unroll 2
        for (int k = 0; k < 64; k++) {
            float a0 = St[(ty*4+0)*ST_STRIDE + k];
            float a1 = St[(ty*4+1)*ST_STRIDE + k];
            float a2 = St[(ty*4+2)*ST_STRIDE + k];
            float a3 = St[(ty*4+3)*ST_STRIDE + k];
            float4 v0 = *(const float4*)&Vs[k*VS_STRIDE + tx*8];
            float4 v1 = *(const float4*)&Vs[k*VS_STRIDE + tx*8 + 4];
            float av[4]  = {a0,a1,a2,a3};
            float bv2[8] = {v0.x,v0.y,v0.z,v0.w,v1.x,v1.y,v1.z,v1.w};
            #pragma unroll
            for (int i = 0; i < 4; i++)
                #pragma unroll
                for (int j = 0; j < 8; j++)
                    o[i][j] = fmaf(av[i], bv2[j], o[i][j]);
        }
    }

    #pragma unroll
    for (int i = 0; i < 4; i++) {
        float inv = 1.0f / lrow[ty*4 + i];
        int n = q0 + ty*4 + i;
        float* p = &d_O[(b*NN + n)*CSd + tx*8];
        *(float4*)p       = make_float4(o[i][0]*inv, o[i][1]*inv, o[i][2]*inv, o[i][3]*inv);
        *((float4*)p + 1) = make_float4(o[i][4]*inv, o[i][5]*inv, o[i][6]*inv, o[i][7]*inv);
    }
}

// ======================= Kernel C: output projection ========================
// grid (N/128, C/128, B), block 256. y[b][c][n] = Wo[c][:] . O[b][n][:] + bo
__global__ __launch_bounds__(256) void oproj_kernel(
    const float* __restrict__ Wo, const float* __restrict__ bo)
{
    __shared__ float Wos[128*36];  // Wos[c][kc]
    __shared__ float Os[32*132];   // Os[kc][n]
    const int b  = blockIdx.z;
    const int c0 = blockIdx.y * 128;
    const int n0 = blockIdx.x * 128;
    const int tid = threadIdx.x;
    const int ty = tid >> 4, tx = tid & 15;

    float acc[8][8];
    #pragma unroll
    for (int i = 0; i < 8; i++)
        #pragma unroll
        for (int j = 0; j < 8; j++) acc[i][j] = 0.f;

    for (int k0 = 0; k0 < CSd; k0 += 32) {
        #pragma unroll
        for (int it = 0; it < 16; it++) {
            int f = tid + it*256;
            int kc = f & 31, c = f >> 5;
            Wos[c*36 + kc] = Wo[(c0 + c)*CSd + k0 + kc];
        }
        #pragma unroll
        for (int it = 0; it < 16; it++) {
            int f = tid + it*256;
            int kc = f & 31, n2 = f >> 5;
            Os[kc*132 + n2] = d_O[(b*NN + n0 + n2)*CSd + k0 + kc];
        }
        __syncthreads();
        #pragma unroll 8
        for (int kc = 0; kc < 32; kc++) {
            float a[8];
            #pragma unroll
            for (int i = 0; i < 8; i++) a[i] = Wos[(ty*8+i)*36 + kc];
            float4 b0 = *(const float4*)&Os[kc*132 + tx*8];
            float4 b1 = *(const float4*)&Os[kc*132 + tx*8 + 4];
            float bbv[8] = {b0.x,b0.y,b0.z,b0.w,b1.x,b1.y,b1.z,b1.w};
            #pragma unroll
            for (int i = 0; i < 8; i++)
                #pragma unroll
                for (int j = 0; j < 8; j++)
                    acc[i][j] = fmaf(a[i], bbv[j], acc[i][j]);
        }
        __syncthreads();
    }

    #pragma unroll
    for (int i = 0; i < 8; i++) {
        int c = c0 + ty*8 + i;
        float bv2 = bo[c];
        float* p = &d_Y[(b*CC + c)*NN + n0 + tx*8];
        *(float4*)p       = make_float4(acc[i][0]+bv2, acc[i][1]+bv2, acc[i][2]+bv2, acc[i][3]+bv2);
        *((float4*)p + 1) = make_float4(acc[i][4]+bv2, acc[i][5]+bv2, acc[i][6]+bv2, acc[i][7]+bv2);
    }
}

// ======================= Kernel D: BN stats (deterministic) =================
__global__ __launch_bounds__(256) void bnstat_kernel(
    const float* __restrict__ gamma, const float* __restrict__ beta)
{
    __shared__ float rs[256], rs2[256];
    const int c = blockIdx.x, tid = threadIdx.x;
    float s = 0.f, s2 = 0.f;
    #pragma unroll 4
    for (int j = 0; j < 64; j++) {
        int idx = tid + j*256;            // over B*N = 16384
        int bb2 = idx >> 12, nn2 = idx & 4095;
        float v = d_Y[(bb2*CC + c)*NN + nn2];
        s += v; s2 += v*v;
    }
    rs[tid] = s; rs2[tid] = s2;
    __syncthreads();
    for (int off = 128; off > 0; off >>= 1) {
        if (tid < off) { rs[tid] += rs[tid+off]; rs2[tid] += rs2[tid+off]; }
        __syncthreads();
    }
    if (tid == 0) {
        float mean = rs[0]  * (1.f/16384.f);
        float var  = rs2[0] * (1.f/16384.f) - mean*mean;
        float sc = gamma[c] * rsqrtf(var + EPSc);
        d_scale[c] = sc;
        d_shift[c] = beta[c] - mean*sc;
    }
}

// ======================= Kernel E: BN affine + ReLU + residual ==============
__global__ __launch_bounds__(256) void epilogue_kernel(
    const float* __restrict__ x, float* __restrict__ out)
{
    int i4 = blockIdx.x*256 + threadIdx.x;     // < 1048576 float4s
    int idx = i4 * 4;
    int c = (idx >> 12) & 255;
    float sc = d_scale[c], sh = d_shift[c];
    float4 y   = *(const float4*)&d_Y[idx];
    float4 xin = ((const float4*)x)[i4];
    float4 r;
    r.x = fmaxf(fmaf(y.x, sc, sh), 0.f) + xin.x;
    r.y = fmaxf(fmaf(y.y, sc, sh), 0.f) + xin.y;
    r.z = fmaxf(fmaf(y.z, sc, sh), 0.f) + xin.z;
    r.w = fmaxf(fmaf(y.w, sc, sh), 0.f) + xin.w;
    ((float4*)out)[i4] = r;
}

// ============================ launch =======================================
extern "C" void kernel_launch(void* const* d_in, const int* in_sizes, int n_in,
                              void* d_out, int out_size)
{
    const float* x     = (const float*)d_in[0];
    const float* Wq    = (const float*)d_in[1];
    const float* bq    = (const float*)d_in[2];
    const float* Wk    = (const float*)d_in[3];
    const float* bk    = (const float*)d_in[4];
    const float* Wv    = (const float*)d_in[5];
    const float* bv    = (const float*)d_in[6];
    const float* Wo    = (const float*)d_in[7];
    const float* bo    = (const float*)d_in[8];
    const float* gamma = (const float*)d_in[9];
    const float* beta  = (const float*)d_in[10];
    float* out = (float*)d_out;

    cudaFuncSetAttribute(attn_kernel,
                         cudaFuncAttributeMaxDynamicSharedMemorySize,
                         ATTN_SMEM_BYTES);

    qkv_kernel<<<dim3(NN/128, BB, 3), 256>>>(x, Wq, bq, Wk, bk, Wv, bv);
    attn_kernel<<<dim3(NN/64, BB), 256, ATTN_SMEM_BYTES>>>();
    oproj_kernel<<<dim3(NN/128, CC/128, BB), 256>>>(Wo, bo);
    bnstat_kernel<<<CC, 256>>>(gamma, beta);
    epilogue_kernel<<<(BB*CC*NN)/4/256, 256>>>(x, out);
}

// round 3
// speedup vs baseline: 1.4699x; 1.4699x over previous
#include <cuda_runtime.h>
#include <math.h>

#define BB   4
#define CC   256
#define CSd  128
#define NN   4096
#define EPSc 1e-5f

typedef unsigned long long ull;

// ---------------- f32x2 packed-math helpers (sm_103a FFMA2) ----------------
__device__ __forceinline__ ull pack2(float x, float y){
    ull r; asm("mov.b64 %0, {%1,%2};" : "=l"(r) : "f"(x), "f"(y)); return r;
}
__device__ __forceinline__ void unpack2(ull v, float& x, float& y){
    asm("mov.b64 {%0,%1}, %2;" : "=f"(x), "=f"(y) : "l"(v));
}
__device__ __forceinline__ ull ffma2(ull a, ull b, ull c){
    ull d; asm("fma.rn.f32x2 %0, %1, %2, %3;" : "=l"(d) : "l"(a), "l"(b), "l"(c)); return d;
}
__device__ __forceinline__ ull fmul2(ull a, ull b){
    ull d; asm("mul.rn.f32x2 %0, %1, %2;" : "=l"(d) : "l"(a), "l"(b)); return d;
}

// ---------------- scratch (device globals; no allocations) ----------------
__device__ float d_Q[BB*CSd*NN];   // [b][cs][n] dim-major
__device__ float d_K[BB*CSd*NN];   // [b][cs][n] dim-major
__device__ float d_V[BB*NN*CSd];   // [b][n][cs] token-major
__device__ float d_O[BB*NN*CSd];   // [b][n][cs] token-major
__device__ float d_Y[BB*CC*NN];    // [b][c][n]
__device__ float d_scale[CC];
__device__ float d_shift[CC];

// ======================= Kernel A: QKV projections =========================
// grid (N/128, B, 3), block 256. Out tile 128(cs) x 128(n), 8x8 microtile, FFMA2.
__global__ __launch_bounds__(256) void qkv_kernel(
    const float* __restrict__ x,
    const float* __restrict__ Wq, const float* __restrict__ bq,
    const float* __restrict__ Wk, const float* __restrict__ bk,
    const float* __restrict__ Wv, const float* __restrict__ bv)
{
    __shared__ float Ws[128*37];   // Ws[cs][kc], stride 37 (conflict-free bcast)
    __shared__ float Xs[32*132];   // Xs[kc][n]
    const int z  = blockIdx.z;     // 0=Q 1=K 2=V
    const int b  = blockIdx.y;
    const int n0 = blockIdx.x * 128;
    const float* W    = (z==0) ? Wq : (z==1) ? Wk : Wv;
    const float* bias = (z==0) ? bq : (z==1) ? bk : bv;
    const int tid = threadIdx.x;
    const int ty = tid >> 4, tx = tid & 15;

    ull acc2[8][4];
    #pragma unroll
    for (int i = 0; i < 8; i++)
        #pragma unroll
        for (int j = 0; j < 4; j++) acc2[i][j] = 0ull;

    for (int k0 = 0; k0 < CC; k0 += 32) {
        #pragma unroll
        for (int it = 0; it < 16; it++) {
            int f = tid + it*256;
            int kc = f & 31, cs = f >> 5;
            Ws[cs*37 + kc] = W[cs*CC + k0 + kc];
        }
        #pragma unroll
        for (int it = 0; it < 16; it++) {
            int f = tid + it*256;
            int nn2 = f & 127, kc = f >> 7;
            Xs[kc*132 + nn2] = x[(b*CC + k0 + kc)*NN + n0 + nn2];
        }
        __syncthreads();
        #pragma unroll 4
        for (int kc = 0; kc < 32; kc++) {
            ull ad[8];
            #pragma unroll
            for (int i = 0; i < 8; i++) {
                float a = Ws[(ty*8+i)*37 + kc];
                ad[i] = pack2(a, a);
            }
            ulonglong2 x0 = *(const ulonglong2*)&Xs[kc*132 + tx*8];
            ulonglong2 x1 = *(const ulonglong2*)&Xs[kc*132 + tx*8 + 4];
            ull bb[4] = {x0.x, x0.y, x1.x, x1.y};
            #pragma unroll
            for (int i = 0; i < 8; i++)
                #pragma unroll
                for (int j = 0; j < 4; j++)
                    acc2[i][j] = ffma2(ad[i], bb[j], acc2[i][j]);
        }
        __syncthreads();
    }

    float accf[8][8];
    #pragma unroll
    for (int i = 0; i < 8; i++)
        #pragma unroll
        for (int j = 0; j < 4; j++)
            unpack2(acc2[i][j], accf[i][2*j], accf[i][2*j+1]);

    float bl[8];
    #pragma unroll
    for (int i = 0; i < 8; i++) bl[i] = bias[ty*8 + i];

    if (z < 2) {
        float* out = (z==0) ? d_Q : d_K;
        #pragma unroll
        for (int i = 0; i < 8; i++) {
            int cs = ty*8 + i;
            float* p = &out[(b*CSd + cs)*NN + n0 + tx*8];
            *(float4*)p       = make_float4(accf[i][0]+bl[i], accf[i][1]+bl[i], accf[i][2]+bl[i], accf[i][3]+bl[i]);
            *((float4*)p + 1) = make_float4(accf[i][4]+bl[i], accf[i][5]+bl[i], accf[i][6]+bl[i], accf[i][7]+bl[i]);
        }
    } else {
        #pragma unroll
        for (int j = 0; j < 8; j++) {
            int n = n0 + tx*8 + j;
            float* p = &d_V[(b*NN + n)*CSd + ty*8];
            *(float4*)p       = make_float4(accf[0][j]+bl[0], accf[1][j]+bl[1], accf[2][j]+bl[2], accf[3][j]+bl[3]);
            *((float4*)p + 1) = make_float4(accf[4][j]+bl[4], accf[5][j]+bl[5], accf[6][j]+bl[6], accf[7][j]+bl[7]);
        }
    }
}

// ======================= Kernel B: flash attention (fp32, FFMA2) ===========
// grid (N/128, B) = 128 CTAs, block 256, ~200KB dynamic smem, 1 CTA/SM.
// BM=128 q, BN=128 keys, d=128. 8x8 microtiles both phases.
// St row address: r*132 + ((r>>3)&1)*4  (ty-parity offset kills PV bcast conflict)
#define ST_ROW(r) ((r)*132 + (((r)>>3)&1)*4)
#define ATTN_SMEM_FLOATS (128*128 + 128*128 + (128*132 + 8) + 3*128)
#define ATTN_SMEM_BYTES  (ATTN_SMEM_FLOATS*4)

__global__ __launch_bounds__(256, 1) void attn_kernel()
{
    extern __shared__ float sm[];
    float* Qt    = sm;                  // [128 d][128 q] stride 128
    float* Bf    = Qt + 128*128;        // K: [128 d][128 k] then V: [128 k][128 d]
    float* St    = Bf + 128*128;        // [128 q][132+off]
    float* mrow  = St + 128*132 + 8;    // [128]
    float* lrow  = mrow + 128;          // [128]
    float* rsrow = lrow + 128;          // [128]

    const int b  = blockIdx.y;
    const int q0 = blockIdx.x * 128;
    const int tid = threadIdx.x;
    const int ty = tid >> 4, tx = tid & 15;

    // load Q tile dim-major (coalesced float4)
    #pragma unroll
    for (int it = 0; it < 16; it++) {
        int g = tid + it*256;               // float4 index over 4096
        int q4 = g & 31, cs = g >> 5;
        *(float4*)&Qt[cs*128 + q4*4] =
            *(const float4*)&d_Q[(b*CSd + cs)*NN + q0 + q4*4];
    }
    if (tid < 128) { mrow[tid] = -1e30f; lrow[tid] = 0.f; }

    int strow[8];
    #pragma unroll
    for (int i = 0; i < 8; i++) strow[i] = (ty*8+i)*132 + (ty&1)*4;

    ull o2[8][4];
    #pragma unroll
    for (int i = 0; i < 8; i++)
        #pragma unroll
        for (int j = 0; j < 4; j++) o2[i][j] = 0ull;

    for (int kt = 0; kt < NN/128; kt++) {
        const int kb = kt * 128;
        __syncthreads();                      // Bf free (prev PV done); Qt ready
        // ---- load K tile: Bf[dim][key] ----
        #pragma unroll
        for (int it = 0; it < 16; it++) {
            int g = tid + it*256;
            int k4 = g & 31, cs = g >> 5;
            *(float4*)&Bf[cs*128 + k4*4] =
                *(const float4*)&d_K[(b*CSd + cs)*NN + kb + k4*4];
        }
        __syncthreads();

        // ---- S = Q^T.K : 8x8 microtile, FFMA2 ----
        ull s2[8][4];
        #pragma unroll
        for (int i = 0; i < 8; i++)
            #pragma unroll
            for (int j = 0; j < 4; j++) s2[i][j] = 0ull;
        #pragma unroll 2
        for (int k = 0; k < 128; k++) {
            float4 qa0 = *(const float4*)&Qt[k*128 + ty*8];
            float4 qa1 = *(const float4*)&Qt[k*128 + ty*8 + 4];
            ull ad[8];
            ad[0]=pack2(qa0.x,qa0.x); ad[1]=pack2(qa0.y,qa0.y);
            ad[2]=pack2(qa0.z,qa0.z); ad[3]=pack2(qa0.w,qa0.w);
            ad[4]=pack2(qa1.x,qa1.x); ad[5]=pack2(qa1.y,qa1.y);
            ad[6]=pack2(qa1.z,qa1.z); ad[7]=pack2(qa1.w,qa1.w);
            ulonglong2 k0v = *(const ulonglong2*)&Bf[k*128 + tx*8];
            ulonglong2 k1v = *(const ulonglong2*)&Bf[k*128 + tx*8 + 4];
            ull bb[4] = {k0v.x, k0v.y, k1v.x, k1v.y};
            #pragma unroll
            for (int i = 0; i < 8; i++)
                #pragma unroll
                for (int j = 0; j < 4; j++)
                    s2[i][j] = ffma2(ad[i], bb[j], s2[i][j]);
        }
        // store logits: St[q][key]
        #pragma unroll
        for (int i = 0; i < 8; i++) {
            *(ulonglong2*)&St[strow[i] + tx*8]     = make_ulonglong2(s2[i][0], s2[i][1]);
            *(ulonglong2*)&St[strow[i] + tx*8 + 4] = make_ulonglong2(s2[i][2], s2[i][3]);
        }
        __syncthreads();                     // St visible; K reads done

        // ---- load V tile into Bf (K is dead) ----
        #pragma unroll
        for (int it = 0; it < 16; it++) {
            int g = tid + it*256;
            int c4 = g & 31, kk = g >> 5;
            *(float4*)&Bf[kk*128 + c4*4] =
                *(const float4*)&d_V[(b*NN + kb + kk)*CSd + c4*4];
        }

        // ---- online softmax: 2 threads/row, rotated sweeps ----
        {
            const int r = tid >> 1, sub = tid & 1;
            const int ro = ST_ROW(r);
            float tm = -1e30f;
            #pragma unroll 8
            for (int t = 0; t < 64; t++) {
                int c = sub*64 + ((t + r) & 63);
                tm = fmaxf(tm, St[ro + c]);
            }
            tm = fmaxf(tm, __shfl_xor_sync(0xffffffffu, tm, 1));
            float mo = mrow[r];
            float nm = fmaxf(mo, tm);
            float sum = 0.f;
            #pragma unroll 8
            for (int t = 0; t < 64; t++) {
                int c = sub*64 + ((t + r) & 63);
                float p = __expf(St[ro + c] - nm);
                St[ro + c] = p;
                sum += p;
            }
            sum += __shfl_xor_sync(0xffffffffu, sum, 1);
            if (sub == 0) {
                float scv = __expf(mo - nm);
                lrow[r] = lrow[r]*scv + sum;
                mrow[r] = nm;
                rsrow[r] = scv;
            }
        }
        __syncthreads();                     // P + V + rsrow ready

        // ---- rescale, then O += P.V : 8x8 microtile, FFMA2 ----
        #pragma unroll
        for (int i = 0; i < 8; i++) {
            float scl = rsrow[ty*8 + i];
            ull sd = pack2(scl, scl);
            #pragma unroll
            for (int j = 0; j < 4; j++) o2[i][j] = fmul2(o2[i][j], sd);
        }
        #pragma unroll 2
        for (int k = 0; k < 128; k++) {
            ull pd[8];
            #pragma unroll
            for (int i = 0; i < 8; i++) {
                float p = St[strow[i] + k];
                pd[i] = pack2(p, p);
            }
            ulonglong2 v0 = *(const ulonglong2*)&Bf[k*128 + tx*8];
            ulonglong2 v1 = *(const ulonglong2*)&Bf[k*128 + tx*8 + 4];
            ull vv[4] = {v0.x, v0.y, v1.x, v1.y};
            #pragma unroll
            for (int i = 0; i < 8; i++)
                #pragma unroll
                for (int j = 0; j < 4; j++)
                    o2[i][j] = ffma2(pd[i], vv[j], o2[i][j]);
        }
    }

    #pragma unroll
    for (int i = 0; i < 8; i++) {
        float inv = 1.0f / lrow[ty*8 + i];
        float of[8];
        #pragma unroll
        for (int j = 0; j < 4; j++) unpack2(o2[i][j], of[2*j], of[2*j+1]);
        int n = q0 + ty*8 + i;
        float* p = &d_O[(b*NN + n)*CSd + tx*8];
        *(float4*)p       = make_float4(of[0]*inv, of[1]*inv, of[2]*inv, of[3]*inv);
        *((float4*)p + 1) = make_float4(of[4]*inv, of[5]*inv, of[6]*inv, of[7]*inv);
    }
}

// ======================= Kernel C: output projection (FFMA2) ===============
// grid (N/128, C/128, B), block 256.
__global__ __launch_bounds__(256) void oproj_kernel(
    const float* __restrict__ Wo, const float* __restrict__ bo)
{
    __shared__ float Wos[128*37];  // Wos[c][kc]
    __shared__ float Os[32*132];   // Os[kc][n]
    const int b  = blockIdx.z;
    const int c0 = blockIdx.y * 128;
    const int n0 = blockIdx.x * 128;
    const int tid = threadIdx.x;
    const int ty = tid >> 4, tx = tid & 15;

    ull acc2[8][4];
    #pragma unroll
    for (int i = 0; i < 8; i++)
        #pragma unroll
        for (int j = 0; j < 4; j++) acc2[i][j] = 0ull;

    for (int k0 = 0; k0 < CSd; k0 += 32) {
        #pragma unroll
        for (int it = 0; it < 16; it++) {
            int f = tid + it*256;
            int kc = f & 31, c = f >> 5;
            Wos[c*37 + kc] = Wo[(c0 + c)*CSd + k0 + kc];
        }
        #pragma unroll
        for (int it = 0; it < 16; it++) {
            int f = tid + it*256;
            int kc = f & 31, n2 = f >> 5;
            Os[kc*132 + n2] = d_O[(b*NN + n0 + n2)*CSd + k0 + kc];
        }
        __syncthreads();
        #pragma unroll 4
        for (int kc = 0; kc < 32; kc++) {
            ull ad[8];
            #pragma unroll
            for (int i = 0; i < 8; i++) {
                float a = Wos[(ty*8+i)*37 + kc];
                ad[i] = pack2(a, a);
            }
            ulonglong2 x0 = *(const ulonglong2*)&Os[kc*132 + tx*8];
            ulonglong2 x1 = *(const ulonglong2*)&Os[kc*132 + tx*8 + 4];
            ull bb[4] = {x0.x, x0.y, x1.x, x1.y};
            #pragma unroll
            for (int i = 0; i < 8; i++)
                #pragma unroll
                for (int j = 0; j < 4; j++)
                    acc2[i][j] = ffma2(ad[i], bb[j], acc2[i][j]);
        }
        __syncthreads();
    }

    #pragma unroll
    for (int i = 0; i < 8; i++) {
        float accf[8];
        #pragma unroll
        for (int j = 0; j < 4; j++) unpack2(acc2[i][j], accf[2*j], accf[2*j+1]);
        int c = c0 + ty*8 + i;
        float bv2 = bo[c];
        float* p = &d_Y[(b*CC + c)*NN + n0 + tx*8];
        *(float4*)p       = make_float4(accf[0]+bv2, accf[1]+bv2, accf[2]+bv2, accf[3]+bv2);
        *((float4*)p + 1) = make_float4(accf[4]+bv2, accf[5]+bv2, accf[6]+bv2, accf[7]+bv2);
    }
}

// ======================= Kernel D: BN stats (deterministic) =================
__global__ __launch_bounds__(256) void bnstat_kernel(
    const float* __restrict__ gamma, const float* __restrict__ beta)
{
    __shared__ float rs[256], rs2[256];
    const int c = blockIdx.x, tid = threadIdx.x;
    float s = 0.f, s2 = 0.f;
    #pragma unroll 4
    for (int j = 0; j < 64; j++) {
        int idx = tid + j*256;            // over B*N = 16384
        int bb2 = idx >> 12, nn2 = idx & 4095;
        float v = d_Y[(bb2*CC + c)*NN + nn2];
        s += v; s2 += v*v;
    }
    rs[tid] = s; rs2[tid] = s2;
    __syncthreads();
    for (int off = 128; off > 0; off >>= 1) {
        if (tid < off) { rs[tid] += rs[tid+off]; rs2[tid] += rs2[tid+off]; }
        __syncthreads();
    }
    if (tid == 0) {
        float mean = rs[0]  * (1.f/16384.f);
        float var  = rs2[0] * (1.f/16384.f) - mean*mean;
        float sc = gamma[c] * rsqrtf(var + EPSc);
        d_scale[c] = sc;
        d_shift[c] = beta[c] - mean*sc;
    }
}

// ======================= Kernel E: BN affine + ReLU + residual ==============
__global__ __launch_bounds__(256) void epilogue_kernel(
    const float* __restrict__ x, float* __restrict__ out)
{
    int i4 = blockIdx.x*256 + threadIdx.x;     // < 1048576 float4s
    int idx = i4 * 4;
    int c = (idx >> 12) & 255;
    float sc = d_scale[c], sh = d_shift[c];
    float4 y   = *(const float4*)&d_Y[idx];
    float4 xin = ((const float4*)x)[i4];
    float4 r;
    r.x = fmaxf(fmaf(y.x, sc, sh), 0.f) + xin.x;
    r.y = fmaxf(fmaf(y.y, sc, sh), 0.f) + xin.y;
    r.z = fmaxf(fmaf(y.z, sc, sh), 0.f) + xin.z;
    r.w = fmaxf(fmaf(y.w, sc, sh), 0.f) + xin.w;
    ((float4*)out)[i4] = r;
}

// ============================ launch =======================================
extern "C" void kernel_launch(void* const* d_in, const int* in_sizes, int n_in,
                              void* d_out, int out_size)
{
    const float* x     = (const float*)d_in[0];
    const float* Wq    = (const float*)d_in[1];
    const float* bq    = (const float*)d_in[2];
    const float* Wk    = (const float*)d_in[3];
    const float* bk    = (const float*)d_in[4];
    const float* Wv    = (const float*)d_in[5];
    const float* bv    = (const float*)d_in[6];
    const float* Wo    = (const float*)d_in[7];
    const float* bo    = (const float*)d_in[8];
    const float* gamma = (const float*)d_in[9];
    const float* beta  = (const float*)d_in[10];
    float* out = (float*)d_out;

    cudaFuncSetAttribute(attn_kernel,
                         cudaFuncAttributeMaxDynamicSharedMemorySize,
                         ATTN_SMEM_BYTES);

    qkv_kernel<<<dim3(NN/128, BB, 3), 256>>>(x, Wq, bq, Wk, bk, Wv, bv);
    attn_kernel<<<dim3(NN/128, BB), 256, ATTN_SMEM_BYTES>>>();
    oproj_kernel<<<dim3(NN/128, CC/128, BB), 256>>>(Wo, bo);
    bnstat_kernel<<<CC, 256>>>(gamma, beta);
    epilogue_kernel<<<(BB*CC*NN)/4/256, 256>>>(x, out);
}